// round 9
// baseline (speedup 1.0000x reference)
#include <cuda_runtime.h>
#include <stdint.h>

// Fixed problem shapes
#define BQ 2
#define NQ 16384
#define SQ 4096
#define CQ 64
#define NS 32
#define OUTC 67
#define NCELL 1000            // 10x10x10 grid, cell = radius = 0.1
#define WARPS_B 8             // centers per ball-query block
#define HB 64                 // prep blocks (all co-resident -> safe spin join)
#define QBLOCKS (BQ * SQ / WARPS_B)   // 1024 query blocks
#define NTILE 2048            // transpose tiles (512 n x 2 c x 2 b)

// Device scratch (no allocations allowed). All sync scalars self-reset each
// run -> pipeline stateless under graph replay.
__device__ float4 g_xyzp[BQ * NQ];                  // packed xyz, cell id in .w
__device__ float4 g_sorted[BQ * NQ];                // cell-sorted xyz, orig idx in .w
__device__ float  g_featT[(size_t)BQ * NQ * CQ];    // features [B,N,C]
__device__ int    g_idx[BQ * SQ * NS];              // final sample indices
__device__ int    g_cellcnt[BQ * NCELL];            // histogram (re-zeroed in scan)
__device__ int    g_cellstart[BQ * (NCELL + 1)];    // exclusive prefix, [1000] = N
__device__ int    g_cellfill[BQ * NCELL];           // scatter cursors
__device__ int    g_arrive1 = 0, g_flag = 0, g_arrive2 = 0;

__device__ __forceinline__ int cell_of(float v) {
    int c = (int)(v * 10.0f);
    return min(9, max(0, c));
}

// ---------------------------------------------------------------------------
// K1: fully fused prep (hist -> scan -> scatter) in one 64-block launch.
// ---------------------------------------------------------------------------
__global__ __launch_bounds__(256)
void prep_fused(const float* __restrict__ xyz) {
    __shared__ int wsum[8], wbase[8];
    __shared__ int sh_role;
    const int t = threadIdx.x;
    const int lane = t & 31, wid = t >> 5;
    const int base = blockIdx.x * (BQ * NQ / HB);   // 512 points per block

    // ---- phase 1: pack + histogram ----
    for (int i = base + t; i < base + BQ * NQ / HB; i += 256) {
        float x = xyz[3 * i + 0], y = xyz[3 * i + 1], z = xyz[3 * i + 2];
        int cell = (cell_of(z) * 10 + cell_of(y)) * 10 + cell_of(x);
        g_xyzp[i] = make_float4(x, y, z, __int_as_float(cell));
        atomicAdd(&g_cellcnt[(i >> 14) * NCELL + cell], 1);
    }
    __threadfence();
    __syncthreads();
    if (t == 0) sh_role = (atomicAdd(&g_arrive1, 1) == HB - 1);
    __syncthreads();

    // ---- phase 2: last-arriving block scans both batches ----
    if (sh_role) {
        for (int b = 0; b < BQ; b++) {
            int cnt4[4];
            int own = 0;
            if (t < 250) {
#pragma unroll
                for (int j = 0; j < 4; j++) {
                    cnt4[j] = g_cellcnt[b * NCELL + 4 * t + j];
                    own += cnt4[j];
                }
            }
            int inc = own;
#pragma unroll
            for (int d = 1; d < 32; d <<= 1) {
                int v = __shfl_up_sync(0xffffffffu, inc, d);
                if (lane >= d) inc += v;
            }
            if (lane == 31) wsum[wid] = inc;
            __syncthreads();
            if (t == 0) {
                int run = 0;
#pragma unroll
                for (int w = 0; w < 8; w++) { wbase[w] = run; run += wsum[w]; }
            }
            __syncthreads();
            if (t < 250) {
                int run = wbase[wid] + inc - own;     // exclusive base
#pragma unroll
                for (int j = 0; j < 4; j++) {
                    int bin = 4 * t + j;
                    g_cellstart[b * (NCELL + 1) + bin] = run;
                    g_cellfill[b * NCELL + bin] = run;
                    g_cellcnt[b * NCELL + bin] = 0;   // stateless for replay
                    run += cnt4[j];
                }
            }
            if (t == 0) g_cellstart[b * (NCELL + 1) + NCELL] = NQ;
            __syncthreads();
        }
        __threadfence();
        __syncthreads();
        if (t == 0) { g_arrive1 = 0; __threadfence(); atomicExch(&g_flag, 1); }
    } else {
        if (t == 0) {
            while (atomicAdd(&g_flag, 0) == 0) __nanosleep(32);
        }
        __syncthreads();
        __threadfence();
    }

    // ---- phase 3: scatter into cell order ----
    for (int i = base + t; i < base + BQ * NQ / HB; i += 256) {
        float4 p = g_xyzp[i];
        int cell = __float_as_int(p.w);
        int b = i >> 14, n = i & (NQ - 1);
        int pos = atomicAdd(&g_cellfill[b * NCELL + cell], 1);
        g_sorted[b * NQ + pos] = make_float4(p.x, p.y, p.z, __int_as_float(n));
    }
    __threadfence();
    __syncthreads();
    if (t == 0) {
        if (atomicAdd(&g_arrive2, 1) == HB - 1) { g_flag = 0; g_arrive2 = 0; }
    }
}

// ---------------------------------------------------------------------------
// K2: fused main. Blocks 0..QBLOCKS-1 = ball query (issue-bound, scheduled
// first); blocks QBLOCKS.. = feature transpose tiles (memory-bound backfill).
// Shared memory is a union: query needs 17KB, transpose 4.2KB.
// ---------------------------------------------------------------------------
__global__ __launch_bounds__(256)
void main_fused(const float* __restrict__ new_xyz,
                const float* __restrict__ feat,
                float* __restrict__ out) {
    __shared__ unsigned sbuf[WARPS_B * (NQ / 32) + WARPS_B * NS];  // 17KB union

    if (blockIdx.x >= QBLOCKS) {
        // ---------------- transpose tile ----------------
        float (*tile)[33] = (float (*)[33])sbuf;
        int id = blockIdx.x - QBLOCKS;
        int n0 = (id & 511) * 32;
        int c0 = ((id >> 9) & 1) * 32;
        int b  = id >> 10;
        int tx = threadIdx.x & 31;
        int ty = threadIdx.x >> 5;                  // 0..7
#pragma unroll
        for (int j = 0; j < 32; j += 8)
            tile[ty + j][tx] = feat[((size_t)b * CQ + (c0 + ty + j)) * NQ + (n0 + tx)];
        __syncthreads();
#pragma unroll
        for (int j = 0; j < 32; j += 8)
            g_featT[((size_t)b * NQ + (n0 + ty + j)) * CQ + (c0 + tx)] = tile[tx][ty + j];
        return;
    }

    // ---------------- ball query ----------------
    const int warp = threadIdx.x >> 5;
    const int lane = threadIdx.x & 31;
    unsigned* mask  = sbuf + warp * (NQ / 32);                   // 2KB, transposed layout
    int*      shidx = (int*)(sbuf + WARPS_B * (NQ / 32)) + warp * NS;

    const int center = blockIdx.x * WARPS_B + warp;
    const int b = center / SQ;
    const int s = center % SQ;

    const float cx = new_xyz[3 * center + 0];
    const float cy = new_xyz[3 * center + 1];
    const float cz = new_xyz[3 * center + 2];
    const float r2 = (float)(0.1 * 0.1);

    // zero bitmask with 128-bit stores
    {
        uint4* m4 = (uint4*)mask;
#pragma unroll
        for (int i = lane; i < NQ / 128; i += 32) m4[i] = make_uint4(0, 0, 0, 0);
    }
    __syncwarp();

    // neighbor cell ranges with guard band against boundary rounding
    const int x0 = max(0, (int)floorf((cx - 0.1f) * 10.0f - 0.002f));
    const int x1 = min(9, (int)floorf((cx + 0.1f) * 10.0f + 0.002f));
    const int y0 = max(0, (int)floorf((cy - 0.1f) * 10.0f - 0.002f));
    const int y1 = min(9, (int)floorf((cy + 0.1f) * 10.0f + 0.002f));
    const int z0 = max(0, (int)floorf((cz - 0.1f) * 10.0f - 0.002f));
    const int z1 = min(9, (int)floorf((cz + 0.1f) * 10.0f + 0.002f));

    const float4* __restrict__ srt = g_sorted + (size_t)b * NQ;
    const int* __restrict__ cs = g_cellstart + b * (NCELL + 1);

    for (int zc = z0; zc <= z1; zc++) {
        for (int yc = y0; yc <= y1; yc++) {
            int rowbase = (zc * 10 + yc) * 10;
            int st = cs[rowbase + x0];
            int en = cs[rowbase + x1 + 1];          // x-contiguous cells
            // branch-free body: tail lanes clamp to en-1; a duplicate hit
            // just re-ORs an already-set bit (idempotent).
            for (int ibase = st; ibase < en; ibase += 32) {
                int i = min(ibase + lane, en - 1);
                float4 p = srt[i];
                float dx = __fadd_rn(cx, -p.x);
                float dy = __fadd_rn(cy, -p.y);
                float dz = __fadd_rn(cz, -p.z);
                float d2 = __fadd_rn(__fadd_rn(__fmul_rn(dx, dx), __fmul_rn(dy, dy)),
                                     __fmul_rn(dz, dz));
                int oi = __float_as_int(p.w);
                int w  = oi >> 5;
                unsigned* addr = &mask[((w & 15) << 5) + (w >> 4)];  // transposed slot
                unsigned bit = 1u << (oi & 31);
                if (d2 < r2) atomicOr(addr, bit);   // single predicated ATOMS
            }
        }
    }
    __syncwarp();

    // single-pass extraction, conflict-free: round j reads mask[j*32 + lane];
    // lane L owns global words 16L..16L+15 (ascending index order preserved).
    unsigned wreg[16];
    int pc = 0;
#pragma unroll
    for (int j = 0; j < 16; j++) {
        wreg[j] = mask[(j << 5) + lane];
        pc += __popc(wreg[j]);
    }
    int inc = pc;
#pragma unroll
    for (int d = 1; d < 32; d <<= 1) {
        int v = __shfl_up_sync(0xffffffffu, inc, d);
        if (lane >= d) inc += v;
    }
    const int cnt  = __shfl_sync(0xffffffffu, inc, 31);
    const int excl = inc - pc;
    if (pc > 0 && excl < NS) {
        int pos = excl;
        int basei = lane * 512;
#pragma unroll
        for (int j = 0; j < 16; j++) {
            unsigned w = wreg[j];
            while (w && pos < NS) {
                int bpos = __ffs(w) - 1;
                w &= w - 1;
                shidx[pos++] = basei + (j << 5) + bpos;
            }
        }
    }
    __syncwarp();

    // lane k owns sample k; pad with first hit, 0 if none
    int myidx = (cnt == 0) ? 0 : shidx[(lane < cnt) ? lane : 0];
    g_idx[center * NS + lane] = myidx;

    // grouped_xyz channels 0..2 (coalesced over lane=k)
    float4 p = g_xyzp[(size_t)b * NQ + myidx];
    const size_t chan_stride = (size_t)SQ * NS;
    float* ob = out + ((size_t)b * OUTC * SQ + s) * NS + lane;
    __stcs(ob + 0 * chan_stride, __fadd_rn(p.x, -cx));
    __stcs(ob + 1 * chan_stride, __fadd_rn(p.y, -cy));
    __stcs(ob + 2 * chan_stride, __fadd_rn(p.z, -cz));
}

// ---------------------------------------------------------------------------
// K3: feature grouping, one 128-thread block per center.
// ---------------------------------------------------------------------------
__global__ __launch_bounds__(128)
void group_feat_kernel(float* __restrict__ out) {
    __shared__ float4 sf4[NS][17];                  // pitch 17 float4 -> conflict-free
    __shared__ int    sidx[NS];

    const int center = blockIdx.x;
    const int b = center / SQ;
    const int s = center % SQ;
    const int tid = threadIdx.x;

    if (tid < NS) sidx[tid] = g_idx[center * NS + tid];
    __syncthreads();

    const float4* __restrict__ ft4 =
        (const float4*)(g_featT + (size_t)b * NQ * CQ);
    const int r  = tid >> 4;       // 0..7
    const int c4 = tid & 15;       // 0..15
#pragma unroll
    for (int r0 = 0; r0 < NS; r0 += 8)
        sf4[r0 + r][c4] = __ldg(ft4 + (size_t)sidx[r0 + r] * 16 + c4);
    __syncthreads();

    const int k = tid & 31;
    const int w = tid >> 5;        // 0..3
    const size_t chan_stride = (size_t)SQ * NS;
    float* ob = out + ((size_t)b * OUTC * SQ + s) * NS + k + 3 * chan_stride;
#pragma unroll
    for (int cc = w; cc < 16; cc += 4) {
        float4 v = sf4[k][cc];
        float* o = ob + (size_t)(4 * cc) * chan_stride;
        __stcs(o + 0 * chan_stride, v.x);
        __stcs(o + 1 * chan_stride, v.y);
        __stcs(o + 2 * chan_stride, v.z);
        __stcs(o + 3 * chan_stride, v.w);
    }
}

// ---------------------------------------------------------------------------
// Launch: 3 kernels total
// ---------------------------------------------------------------------------
extern "C" void kernel_launch(void* const* d_in, const int* in_sizes, int n_in,
                              void* d_out, int out_size) {
    const float* xyz     = (const float*)d_in[0];   // [B,N,3]
    const float* new_xyz = (const float*)d_in[1];   // [B,S,3]
    const float* feat    = (const float*)d_in[2];   // [B,C,N]
    float* out = (float*)d_out;                     // [B,67,S,NS]

    prep_fused<<<HB, 256>>>(xyz);                   // hist + scan + scatter
    main_fused<<<QBLOCKS + NTILE, 256>>>(new_xyz, feat, out);  // query + transpose
    group_feat_kernel<<<BQ * SQ, 128>>>(out);
}

// round 10
// speedup vs baseline: 1.2192x; 1.2192x over previous
#include <cuda_runtime.h>
#include <stdint.h>

// Fixed problem shapes
#define BQ 2
#define NQ 16384
#define SQ 4096
#define CQ 64
#define NS 32
#define OUTC 67
#define NCELL 1000            // 10x10x10 grid, cell = radius = 0.1
#define WARPS_B 8             // centers per query block
#define HB 64                 // wide hist/scatter blocks
#define NTILE 2048            // transpose tiles (512 n x 2 c x 2 b)
#define QBLOCKS (BQ * SQ / WARPS_B)   // 1024 query blocks
#define STP 17                // float4 pitch for staging (known conflict-ok)

// Device scratch (no allocations allowed). g_cellcnt starts zero (static
// init) and is re-zeroed by k2 each replay -> pipeline stateless under graphs.
__device__ float4 g_xyzp[BQ * NQ];                  // packed xyz, cell id in .w
__device__ float4 g_sorted[BQ * NQ];                // cell-sorted xyz, orig idx in .w
__device__ float  g_featT[(size_t)BQ * NQ * CQ];    // features [B,N,C]
__device__ int    g_cellcnt[BQ * NCELL];            // histogram
__device__ int    g_cellstart[BQ * (NCELL + 1)];    // exclusive prefix, [1000] = N
__device__ int    g_cellfill[BQ * NCELL];           // scatter cursors

__device__ __forceinline__ int cell_of(float v) {
    int c = (int)(v * 10.0f);
    return min(9, max(0, c));
}

// one 32x32 transpose tile of [B,C,N] -> [B,N,C]; id in [0, NTILE)
__device__ __forceinline__ void transpose_tile(const float* __restrict__ feat, int id) {
    __shared__ float tile[32][33];
    int n0 = (id & 511) * 32;
    int c0 = ((id >> 9) & 1) * 32;
    int b  = id >> 10;
    int tx = threadIdx.x & 31;
    int ty = threadIdx.x >> 5;                      // 0..7
#pragma unroll
    for (int j = 0; j < 32; j += 8)
        tile[ty + j][tx] = feat[((size_t)b * CQ + (c0 + ty + j)) * NQ + (n0 + tx)];
    __syncthreads();
#pragma unroll
    for (int j = 0; j < 32; j += 8)
        g_featT[((size_t)b * NQ + (n0 + ty + j)) * CQ + (c0 + tx)] = tile[tx][ty + j];
}

// ---------------------------------------------------------------------------
// K1: blocks 0..HB-1 = pack + global-atomic histogram; rest = ALL transpose
// ---------------------------------------------------------------------------
__global__ __launch_bounds__(256)
void k1_hist(const float* __restrict__ xyz, const float* __restrict__ feat) {
    if (blockIdx.x < HB) {
        int i = blockIdx.x * (BQ * NQ / HB) + threadIdx.x;   // 512 pts per block
        int end = (blockIdx.x + 1) * (BQ * NQ / HB);
        for (; i < end; i += 256) {
            float x = xyz[3 * i + 0], y = xyz[3 * i + 1], z = xyz[3 * i + 2];
            int cell = (cell_of(z) * 10 + cell_of(y)) * 10 + cell_of(x);
            g_xyzp[i] = make_float4(x, y, z, __int_as_float(cell));
            int b = i >> 14;
            atomicAdd(&g_cellcnt[b * NCELL + cell], 1);
        }
    } else {
        transpose_tile(feat, blockIdx.x - HB);               // all 2048 tiles
    }
}

// ---------------------------------------------------------------------------
// K2: per-batch scan over 1000 cells; re-zeroes counts, fills starts+cursors
// ---------------------------------------------------------------------------
__global__ __launch_bounds__(256)
void k2_scan() {
    __shared__ int wsum[8], wbase[8];
    const int b = blockIdx.x;
    const int t = threadIdx.x;
    const int lane = t & 31, wid = t >> 5;

    int cnt4[4];
    int own = 0;
    if (t < 250) {
#pragma unroll
        for (int j = 0; j < 4; j++) {
            cnt4[j] = g_cellcnt[b * NCELL + 4 * t + j];
            own += cnt4[j];
        }
    }
    int inc = own;
#pragma unroll
    for (int d = 1; d < 32; d <<= 1) {
        int v = __shfl_up_sync(0xffffffffu, inc, d);
        if (lane >= d) inc += v;
    }
    if (lane == 31) wsum[wid] = inc;
    __syncthreads();
    if (t == 0) {
        int run = 0;
#pragma unroll
        for (int w = 0; w < 8; w++) { wbase[w] = run; run += wsum[w]; }
    }
    __syncthreads();
    if (t < 250) {
        int run = wbase[wid] + inc - own;            // exclusive base
#pragma unroll
        for (int j = 0; j < 4; j++) {
            int bin = 4 * t + j;
            g_cellstart[b * (NCELL + 1) + bin] = run;
            g_cellfill[b * NCELL + bin] = run;
            g_cellcnt[b * NCELL + bin] = 0;          // stateless for replay
            run += cnt4[j];
        }
    }
    if (t == 0) g_cellstart[b * (NCELL + 1) + NCELL] = NQ;
}

// ---------------------------------------------------------------------------
// K3: scatter into cell order (cell id cached in g_xyzp.w)
// ---------------------------------------------------------------------------
__global__ __launch_bounds__(256)
void k3_scatter() {
    int i = blockIdx.x * (BQ * NQ / HB) + threadIdx.x;
    int end = (blockIdx.x + 1) * (BQ * NQ / HB);
    for (; i < end; i += 256) {
        float4 p = g_xyzp[i];
        int cell = __float_as_int(p.w);
        int b = i >> 14, n = i & (NQ - 1);
        int pos = atomicAdd(&g_cellfill[b * NCELL + cell], 1);
        g_sorted[b * NQ + pos] = make_float4(p.x, p.y, p.z, __int_as_float(n));
    }
}

// ---------------------------------------------------------------------------
// K4: fused ball query + feature grouping.
// Phase A (per warp): grid ball query with transposed smem bitmask,
//   single-pass conflict-free extraction, padded indices -> shidx, xyz out.
// Phase B (block-cooperative): for each of the 8 centers, stage its 32
//   feature rows through smem (mask region reused) and write channels 3..66
//   with fully coalesced 128B stores.
// ---------------------------------------------------------------------------
__global__ __launch_bounds__(256)
void query_group_kernel(const float* __restrict__ new_xyz,
                        float* __restrict__ out) {
    __shared__ __align__(16) unsigned sbuf[WARPS_B * (NQ / 32)];  // 16KB: masks / stage
    __shared__ int shidx[WARPS_B][NS];              // padded final indices

    const int tid  = threadIdx.x;
    const int warp = tid >> 5;
    const int lane = tid & 31;
    const int center = blockIdx.x * WARPS_B + warp;
    const int b = center / SQ;
    const int s = center % SQ;
    const size_t chan_stride = (size_t)SQ * NS;

    // ---------------- Phase A: ball query ----------------
    {
        unsigned* mask = sbuf + warp * (NQ / 32);   // transposed bitmask, 2KB

        const float cx = new_xyz[3 * center + 0];
        const float cy = new_xyz[3 * center + 1];
        const float cz = new_xyz[3 * center + 2];
        const float r2 = (float)(0.1 * 0.1);

        {
            uint4* m4 = (uint4*)mask;
#pragma unroll
            for (int i = lane; i < NQ / 128; i += 32) m4[i] = make_uint4(0, 0, 0, 0);
        }
        __syncwarp();

        // neighbor cell ranges with guard band against boundary rounding
        const int x0 = max(0, (int)floorf((cx - 0.1f) * 10.0f - 0.002f));
        const int x1 = min(9, (int)floorf((cx + 0.1f) * 10.0f + 0.002f));
        const int y0 = max(0, (int)floorf((cy - 0.1f) * 10.0f - 0.002f));
        const int y1 = min(9, (int)floorf((cy + 0.1f) * 10.0f + 0.002f));
        const int z0 = max(0, (int)floorf((cz - 0.1f) * 10.0f - 0.002f));
        const int z1 = min(9, (int)floorf((cz + 0.1f) * 10.0f + 0.002f));

        const float4* __restrict__ srt = g_sorted + (size_t)b * NQ;
        const int* __restrict__ cs = g_cellstart + b * (NCELL + 1);

        for (int zc = z0; zc <= z1; zc++) {
            for (int yc = y0; yc <= y1; yc++) {
                int rowbase = (zc * 10 + yc) * 10;
                int st = cs[rowbase + x0];
                int en = cs[rowbase + x1 + 1];      // x-contiguous cells
                // branch-free: tail lanes clamp to en-1 (duplicate OR is idempotent)
                for (int ibase = st; ibase < en; ibase += 32) {
                    int i = min(ibase + lane, en - 1);
                    float4 p = srt[i];
                    float dx = __fadd_rn(cx, -p.x);
                    float dy = __fadd_rn(cy, -p.y);
                    float dz = __fadd_rn(cz, -p.z);
                    float d2 = __fadd_rn(__fadd_rn(__fmul_rn(dx, dx), __fmul_rn(dy, dy)),
                                         __fmul_rn(dz, dz));
                    int oi = __float_as_int(p.w);
                    int w  = oi >> 5;
                    unsigned* addr = &mask[((w & 15) << 5) + (w >> 4)];
                    unsigned bit = 1u << (oi & 31);
                    if (d2 < r2) atomicOr(addr, bit);
                }
            }
        }
        __syncwarp();

        // conflict-free single-pass extraction (ascending original index)
        unsigned wreg[16];
        int pc = 0;
#pragma unroll
        for (int j = 0; j < 16; j++) {
            wreg[j] = mask[(j << 5) + lane];
            pc += __popc(wreg[j]);
        }
        int inc = pc;
#pragma unroll
        for (int d = 1; d < 32; d <<= 1) {
            int v = __shfl_up_sync(0xffffffffu, inc, d);
            if (lane >= d) inc += v;
        }
        const int cnt  = __shfl_sync(0xffffffffu, inc, 31);
        const int excl = inc - pc;
        if (pc > 0 && excl < NS) {
            int pos = excl;
            int basei = lane * 512;
#pragma unroll
            for (int j = 0; j < 16; j++) {
                unsigned w = wreg[j];
                while (w && pos < NS) {
                    int bpos = __ffs(w) - 1;
                    w &= w - 1;
                    shidx[warp][pos++] = basei + (j << 5) + bpos;
                }
            }
        }
        __syncwarp();

        // materialize padded index (pad with first hit, 0 if none)
        int myidx = (cnt == 0) ? 0 : shidx[warp][(lane < cnt) ? lane : 0];
        __syncwarp();
        shidx[warp][lane] = myidx;

        // grouped_xyz channels 0..2 (coalesced over lane=k)
        float4 p = g_xyzp[(size_t)b * NQ + myidx];
        float* ob = out + ((size_t)b * OUTC * SQ + s) * NS + lane;
        __stcs(ob + 0 * chan_stride, __fadd_rn(p.x, -cx));
        __stcs(ob + 1 * chan_stride, __fadd_rn(p.y, -cy));
        __stcs(ob + 2 * chan_stride, __fadd_rn(p.z, -cz));
    }
    __syncthreads();   // masks dead; shidx finalized for all 8 centers

    // ---------------- Phase B: feature grouping ----------------
    float4* stage = (float4*)sbuf;                  // 32 x STP float4 = 8.5KB
    const int r  = tid >> 4;                        // 0..15
    const int c4 = tid & 15;                        // 0..15
    const int k  = tid & 31;
    const int w  = tid >> 5;                        // 0..7

    const int bblk = (blockIdx.x * WARPS_B) / SQ;   // batch uniform per block
    const float4* __restrict__ ft4 =
        (const float4*)(g_featT + (size_t)bblk * NQ * CQ);

#pragma unroll 1
    for (int c = 0; c < WARPS_B; c++) {
        const int center_c = blockIdx.x * WARPS_B + c;
        const int sc = center_c % SQ;

        // stage 32 rows x 16 float4 (coalesced 256B row reads)
        float4 v0 = __ldg(ft4 + (size_t)shidx[c][r]      * 16 + c4);
        float4 v1 = __ldg(ft4 + (size_t)shidx[c][r + 16] * 16 + c4);
        stage[r * STP + c4]        = v0;
        stage[(r + 16) * STP + c4] = v1;
        __syncthreads();

        // write channels 3..66: lane=k coalesced 128B stores
        float* ob = out + ((size_t)bblk * OUTC * SQ + sc) * NS + k + 3 * chan_stride;
#pragma unroll
        for (int cc = w; cc < 16; cc += 8) {
            float4 v = stage[k * STP + cc];
            float* o = ob + (size_t)(4 * cc) * chan_stride;
            __stcs(o + 0 * chan_stride, v.x);
            __stcs(o + 1 * chan_stride, v.y);
            __stcs(o + 2 * chan_stride, v.z);
            __stcs(o + 3 * chan_stride, v.w);
        }
        __syncthreads();                            // before next center reuses stage
    }
}

// ---------------------------------------------------------------------------
// Launch
// ---------------------------------------------------------------------------
extern "C" void kernel_launch(void* const* d_in, const int* in_sizes, int n_in,
                              void* d_out, int out_size) {
    const float* xyz     = (const float*)d_in[0];   // [B,N,3]
    const float* new_xyz = (const float*)d_in[1];   // [B,S,3]
    const float* feat    = (const float*)d_in[2];   // [B,C,N]
    float* out = (float*)d_out;                     // [B,67,S,NS]

    k1_hist<<<HB + NTILE, 256>>>(xyz, feat);        // hist + all transpose
    k2_scan<<<BQ, 256>>>();                         // per-batch cell scan
    k3_scatter<<<HB, 256>>>();                      // cell-order scatter

    query_group_kernel<<<QBLOCKS, 256>>>(new_xyz, out);   // fused query + group
}

// round 12
// speedup vs baseline: 1.2214x; 1.0017x over previous
#include <cuda_runtime.h>
#include <stdint.h>

// Fixed problem shapes
#define BQ 2
#define NQ 16384
#define SQ 4096
#define CQ 64
#define NS 32
#define OUTC 67
#define NCELL 1000            // 10x10x10 grid, cell = radius = 0.1
#define WARPS_B 8             // centers per query block
#define HB 64                 // wide hist/scatter blocks
#define NTILE 2048            // transpose tiles (512 n x 2 c x 2 b)
#define QBLOCKS (BQ * SQ / WARPS_B)   // 1024 query blocks
#define STP 17                // float4 pitch for staging (conflict-free)
#define CPB (BQ * SQ / HB)    // centers per hist/scatter block = 128

// Device scratch (no allocations allowed). Count arrays start zero (static
// init) and are re-zeroed by k2 each replay -> stateless under graph replay.
__device__ float4 g_xyzp[BQ * NQ];                  // packed xyz, cell id in .w
__device__ float4 g_sorted[BQ * NQ];                // cell-sorted xyz, orig idx in .w
__device__ float4 g_cxyz[BQ * SQ];                  // packed centers, cell id in .w
__device__ float4 g_csorted[BQ * SQ];               // cell-sorted centers, orig s in .w
__device__ float  g_featT[(size_t)BQ * NQ * CQ];    // features [B,N,C]
__device__ int    g_cellcnt[BQ * NCELL];            // point histogram
__device__ int    g_cellstart[BQ * (NCELL + 1)];    // point exclusive prefix
__device__ int    g_cellfill[BQ * NCELL];           // point scatter cursors
__device__ int    g_ccnt[BQ * NCELL];               // center histogram
__device__ int    g_cfill[BQ * NCELL];              // center scatter cursors

__device__ __forceinline__ int cell_of(float v) {
    int c = (int)(v * 10.0f);
    return min(9, max(0, c));
}

// one 32x32 transpose tile of [B,C,N] -> [B,N,C]; id in [0, NTILE)
__device__ __forceinline__ void transpose_tile(const float* __restrict__ feat, int id) {
    __shared__ float tile[32][33];
    int n0 = (id & 511) * 32;
    int c0 = ((id >> 9) & 1) * 32;
    int b  = id >> 10;
    int tx = threadIdx.x & 31;
    int ty = threadIdx.x >> 5;                      // 0..7
#pragma unroll
    for (int j = 0; j < 32; j += 8)
        tile[ty + j][tx] = feat[((size_t)b * CQ + (c0 + ty + j)) * NQ + (n0 + tx)];
    __syncthreads();
#pragma unroll
    for (int j = 0; j < 32; j += 8)
        g_featT[((size_t)b * NQ + (n0 + ty + j)) * CQ + (c0 + tx)] = tile[tx][ty + j];
}

// ---------------------------------------------------------------------------
// K1: blocks 0..HB-1 = pack + histogram for points AND centers;
//     rest = ALL transpose tiles
// ---------------------------------------------------------------------------
__global__ __launch_bounds__(256)
void k1_hist(const float* __restrict__ xyz,
             const float* __restrict__ new_xyz,
             const float* __restrict__ feat) {
    if (blockIdx.x < HB) {
        // points: 512 per block
        int i = blockIdx.x * (BQ * NQ / HB) + threadIdx.x;
        int end = (blockIdx.x + 1) * (BQ * NQ / HB);
        for (; i < end; i += 256) {
            float x = xyz[3 * i + 0], y = xyz[3 * i + 1], z = xyz[3 * i + 2];
            int cell = (cell_of(z) * 10 + cell_of(y)) * 10 + cell_of(x);
            g_xyzp[i] = make_float4(x, y, z, __int_as_float(cell));
            atomicAdd(&g_cellcnt[(i >> 14) * NCELL + cell], 1);
        }
        // centers: CPB=128 per block, one per thread (guarded!)
        if (threadIdx.x < CPB) {
            int j = blockIdx.x * CPB + threadIdx.x;
            float x = new_xyz[3 * j + 0], y = new_xyz[3 * j + 1], z = new_xyz[3 * j + 2];
            int cell = (cell_of(z) * 10 + cell_of(y)) * 10 + cell_of(x);
            g_cxyz[j] = make_float4(x, y, z, __int_as_float(cell));
            atomicAdd(&g_ccnt[(j >> 12) * NCELL + cell], 1);
        }
    } else {
        transpose_tile(feat, blockIdx.x - HB);
    }
}

// ---------------------------------------------------------------------------
// K2: 4 blocks. 0,1 = point-cell scan (writes cellstart+cursors);
//               2,3 = center-cell scan (cursors only). Re-zeroes counts.
// ---------------------------------------------------------------------------
__global__ __launch_bounds__(256)
void k2_scan() {
    __shared__ int wsum[8], wbase[8];
    const int which = blockIdx.x >> 1;              // 0 = points, 1 = centers
    const int b = blockIdx.x & 1;
    const int t = threadIdx.x;
    const int lane = t & 31, wid = t >> 5;

    int* cnt  = (which ? g_ccnt  : g_cellcnt) + b * NCELL;
    int* fill = (which ? g_cfill : g_cellfill) + b * NCELL;

    int cnt4[4];
    int own = 0;
    if (t < 250) {
#pragma unroll
        for (int j = 0; j < 4; j++) { cnt4[j] = cnt[4 * t + j]; own += cnt4[j]; }
    }
    int inc = own;
#pragma unroll
    for (int d = 1; d < 32; d <<= 1) {
        int v = __shfl_up_sync(0xffffffffu, inc, d);
        if (lane >= d) inc += v;
    }
    if (lane == 31) wsum[wid] = inc;
    __syncthreads();
    if (t == 0) {
        int run = 0;
#pragma unroll
        for (int w = 0; w < 8; w++) { wbase[w] = run; run += wsum[w]; }
    }
    __syncthreads();
    if (t < 250) {
        int run = wbase[wid] + inc - own;            // exclusive base
#pragma unroll
        for (int j = 0; j < 4; j++) {
            int bin = 4 * t + j;
            if (which == 0) g_cellstart[b * (NCELL + 1) + bin] = run;
            fill[bin] = run;
            cnt[bin] = 0;                            // stateless for replay
            run += cnt4[j];
        }
    }
    if (t == 0 && which == 0) g_cellstart[b * (NCELL + 1) + NCELL] = NQ;
}

// ---------------------------------------------------------------------------
// K3: scatter points and centers into cell order
// ---------------------------------------------------------------------------
__global__ __launch_bounds__(256)
void k3_scatter() {
    int i = blockIdx.x * (BQ * NQ / HB) + threadIdx.x;
    int end = (blockIdx.x + 1) * (BQ * NQ / HB);
    for (; i < end; i += 256) {
        float4 p = g_xyzp[i];
        int cell = __float_as_int(p.w);
        int b = i >> 14, n = i & (NQ - 1);
        int pos = atomicAdd(&g_cellfill[b * NCELL + cell], 1);
        g_sorted[b * NQ + pos] = make_float4(p.x, p.y, p.z, __int_as_float(n));
    }
    // centers: CPB=128 per block, one per thread (guarded!)
    if (threadIdx.x < CPB) {
        int j = blockIdx.x * CPB + threadIdx.x;
        float4 p = g_cxyz[j];
        int cell = __float_as_int(p.w);
        int b = j >> 12, s = j & (SQ - 1);
        int pos = atomicAdd(&g_cfill[b * NCELL + cell], 1);
        g_csorted[b * SQ + pos] = make_float4(p.x, p.y, p.z, __int_as_float(s));
    }
}

// ---------------------------------------------------------------------------
// K4: fused ball query + grouping over CELL-SORTED centers (block's 8 warps
// share candidate cells -> L1-resident candidate rows).
// ---------------------------------------------------------------------------
__global__ __launch_bounds__(256)
void query_group_kernel(float* __restrict__ out) {
    __shared__ __align__(16) unsigned sbuf[WARPS_B * (NQ / 32)];  // 16KB masks / stage
    __shared__ int shidx[WARPS_B][NS];              // padded final indices
    __shared__ int sh_s[WARPS_B];                   // original center ids

    const int tid  = threadIdx.x;
    const int warp = tid >> 5;
    const int lane = tid & 31;
    const int csort = blockIdx.x * WARPS_B + warp;  // sorted center slot
    const int b = csort / SQ;                       // batch-major sorted layout
    const size_t chan_stride = (size_t)SQ * NS;

    // ---------------- Phase A: ball query ----------------
    {
        unsigned* mask = sbuf + warp * (NQ / 32);   // transposed bitmask, 2KB

        float4 cp = g_csorted[csort];
        const float cx = cp.x, cy = cp.y, cz = cp.z;
        const int   s  = __float_as_int(cp.w);      // original center index
        const float r2 = (float)(0.1 * 0.1);
        if (lane == 0) sh_s[warp] = s;

        {
            uint4* m4 = (uint4*)mask;
#pragma unroll
            for (int i = lane; i < NQ / 128; i += 32) m4[i] = make_uint4(0, 0, 0, 0);
        }
        __syncwarp();

        // neighbor cell ranges with guard band against boundary rounding
        const int x0 = max(0, (int)floorf((cx - 0.1f) * 10.0f - 0.002f));
        const int x1 = min(9, (int)floorf((cx + 0.1f) * 10.0f + 0.002f));
        const int y0 = max(0, (int)floorf((cy - 0.1f) * 10.0f - 0.002f));
        const int y1 = min(9, (int)floorf((cy + 0.1f) * 10.0f + 0.002f));
        const int z0 = max(0, (int)floorf((cz - 0.1f) * 10.0f - 0.002f));
        const int z1 = min(9, (int)floorf((cz + 0.1f) * 10.0f + 0.002f));

        const float4* __restrict__ srt = g_sorted + (size_t)b * NQ;
        const int* __restrict__ cs = g_cellstart + b * (NCELL + 1);

        for (int zc = z0; zc <= z1; zc++) {
            for (int yc = y0; yc <= y1; yc++) {
                int rowbase = (zc * 10 + yc) * 10;
                int st = cs[rowbase + x0];
                int en = cs[rowbase + x1 + 1];      // x-contiguous cells
                // branch-free: tail lanes clamp to en-1 (duplicate OR idempotent)
                for (int ibase = st; ibase < en; ibase += 32) {
                    int i = min(ibase + lane, en - 1);
                    float4 p = srt[i];
                    float dx = __fadd_rn(cx, -p.x);
                    float dy = __fadd_rn(cy, -p.y);
                    float dz = __fadd_rn(cz, -p.z);
                    float d2 = __fadd_rn(__fadd_rn(__fmul_rn(dx, dx), __fmul_rn(dy, dy)),
                                         __fmul_rn(dz, dz));
                    int oi = __float_as_int(p.w);
                    int w  = oi >> 5;
                    unsigned* addr = &mask[((w & 15) << 5) + (w >> 4)];
                    unsigned bit = 1u << (oi & 31);
                    if (d2 < r2) atomicOr(addr, bit);
                }
            }
        }
        __syncwarp();

        // conflict-free single-pass extraction (ascending original index)
        unsigned wreg[16];
        int pc = 0;
#pragma unroll
        for (int j = 0; j < 16; j++) {
            wreg[j] = mask[(j << 5) + lane];
            pc += __popc(wreg[j]);
        }
        int inc = pc;
#pragma unroll
        for (int d = 1; d < 32; d <<= 1) {
            int v = __shfl_up_sync(0xffffffffu, inc, d);
            if (lane >= d) inc += v;
        }
        const int cnt  = __shfl_sync(0xffffffffu, inc, 31);
        const int excl = inc - pc;
        if (pc > 0 && excl < NS) {
            int pos = excl;
            int basei = lane * 512;
#pragma unroll
            for (int j = 0; j < 16; j++) {
                unsigned w = wreg[j];
                while (w && pos < NS) {
                    int bpos = __ffs(w) - 1;
                    w &= w - 1;
                    shidx[warp][pos++] = basei + (j << 5) + bpos;
                }
            }
        }
        __syncwarp();

        // materialize padded index (pad with first hit, 0 if none)
        int myidx = (cnt == 0) ? 0 : shidx[warp][(lane < cnt) ? lane : 0];
        __syncwarp();
        shidx[warp][lane] = myidx;

        // grouped_xyz channels 0..2 (coalesced over lane=k)
        float4 p = g_xyzp[(size_t)b * NQ + myidx];
        float* ob = out + ((size_t)b * OUTC * SQ + s) * NS + lane;
        __stcs(ob + 0 * chan_stride, __fadd_rn(p.x, -cx));
        __stcs(ob + 1 * chan_stride, __fadd_rn(p.y, -cy));
        __stcs(ob + 2 * chan_stride, __fadd_rn(p.z, -cz));
    }
    __syncthreads();   // masks dead; shidx + sh_s finalized

    // ---------------- Phase B: feature grouping (double-buffered) ----------
    float4* stage = (float4*)sbuf;                  // 32 x STP float4 = 8.5KB
    const int r  = tid >> 4;                        // 0..15
    const int c4 = tid & 15;                        // 0..15
    const int k  = tid & 31;
    const int w  = tid >> 5;                        // 0..7

    const float4* __restrict__ ft4 =
        (const float4*)(g_featT + (size_t)b * NQ * CQ);

    float4 v0 = __ldg(ft4 + (size_t)shidx[0][r]      * 16 + c4);
    float4 v1 = __ldg(ft4 + (size_t)shidx[0][r + 16] * 16 + c4);

#pragma unroll 1
    for (int c = 0; c < WARPS_B; c++) {
        stage[r * STP + c4]        = v0;
        stage[(r + 16) * STP + c4] = v1;
        __syncthreads();

        if (c + 1 < WARPS_B) {                      // prefetch next center
            v0 = __ldg(ft4 + (size_t)shidx[c + 1][r]      * 16 + c4);
            v1 = __ldg(ft4 + (size_t)shidx[c + 1][r + 16] * 16 + c4);
        }

        // write channels 3..66: lane=k coalesced 128B stores
        const int sc = sh_s[c];
        float* ob = out + ((size_t)b * OUTC * SQ + sc) * NS + k + 3 * chan_stride;
#pragma unroll
        for (int cc = w; cc < 16; cc += 8) {
            float4 v = stage[k * STP + cc];
            float* o = ob + (size_t)(4 * cc) * chan_stride;
            __stcs(o + 0 * chan_stride, v.x);
            __stcs(o + 1 * chan_stride, v.y);
            __stcs(o + 2 * chan_stride, v.z);
            __stcs(o + 3 * chan_stride, v.w);
        }
        __syncthreads();                            // stage free for next center
    }
}

// ---------------------------------------------------------------------------
// Launch
// ---------------------------------------------------------------------------
extern "C" void kernel_launch(void* const* d_in, const int* in_sizes, int n_in,
                              void* d_out, int out_size) {
    const float* xyz     = (const float*)d_in[0];   // [B,N,3]
    const float* new_xyz = (const float*)d_in[1];   // [B,S,3]
    const float* feat    = (const float*)d_in[2];   // [B,C,N]
    float* out = (float*)d_out;                     // [B,67,S,NS]

    k1_hist<<<HB + NTILE, 256>>>(xyz, new_xyz, feat);  // hist (pts+centers) + transpose
    k2_scan<<<2 * BQ, 256>>>();                        // point + center cell scans
    k3_scatter<<<HB, 256>>>();                         // scatter points + centers

    query_group_kernel<<<QBLOCKS, 256>>>(out);         // fused query + group
}